// round 1
// baseline (speedup 1.0000x reference)
#include <cuda_runtime.h>
#include <cuda_bf16.h>
#include <cstdint>

typedef unsigned long long u64;
typedef unsigned int u32;

// ---------------- scratch (no allocations allowed) ----------------
__device__ float g_pre_ox[512 * 64];
__device__ float g_pre_tp[512 * 64];
__device__ float g_pts[512 * 1000 * 2];
__device__ float g_targets[512 * 1000 * 2];
__device__ float g_off_part[512 * 8];
__device__ float g_cls[512];
__device__ float g_endsum[512];

// ---------------- f32x2 packed helpers ----------------
__device__ __forceinline__ u64 pack2(float lo, float hi) {
    u64 r; asm("mov.b64 %0, {%1, %2};" : "=l"(r) : "f"(lo), "f"(hi)); return r;
}
__device__ __forceinline__ void unpack2(u64 v, float& lo, float& hi) {
    asm("mov.b64 {%0, %1}, %2;" : "=f"(lo), "=f"(hi) : "l"(v));
}
__device__ __forceinline__ u64 fma2(u64 a, u64 b, u64 c) {
    u64 d; asm("fma.rn.f32x2 %0, %1, %2, %3;" : "=l"(d) : "l"(a), "l"(b), "l"(c)); return d;
}

__device__ __forceinline__ float sl1(float z) {
    float d = fabsf(z);
    return d < 1.0f ? 0.5f * d * d : d - 0.5f;
}

// LayerNorm (eps 1e-5) + exact GELU, all in registers (lane = point)
__device__ __forceinline__ void ln_gelu(float* h, const float* g, const float* be) {
    float m = 0.f;
#pragma unroll
    for (int c = 0; c < 64; c++) m += h[c];
    m *= 0.015625f;
    float v = 0.f;
#pragma unroll
    for (int c = 0; c < 64; c++) { float d = h[c] - m; v += d * d; }
    v *= 0.015625f;
    float r = rsqrtf(v + 1e-5f);
#pragma unroll
    for (int c = 0; c < 64; c++) {
        float z = (h[c] - m) * r * g[c] + be[c];
        h[c] = z * ((erff(z * 0.70710678118654752f) + 1.0f) * 0.5f);
    }
}

// ---------------- K0: per-batch precompute of feat@W1 constant part ----------------
__global__ void precompute_kernel(const float* __restrict__ at, const float* __restrict__ vf,
                                  const float* __restrict__ ox_w1, const float* __restrict__ ox_b1,
                                  const float* __restrict__ tp_w1, const float* __restrict__ tp_b1) {
    __shared__ float s_vf[64], s_at[64];
    int b = blockIdx.x, c = threadIdx.x;
    s_vf[c] = vf[b * 64 + c];
    s_at[c] = at[b * 64 + c];
    __syncthreads();
    float a = ox_b1[c], t = tp_b1[c];
#pragma unroll 8
    for (int k = 0; k < 64; k++) {
        a += s_vf[k] * ox_w1[k * 64 + c] + s_at[k] * ox_w1[(64 + k) * 64 + c];
        t += s_vf[k] * tp_w1[k * 64 + c] + s_at[k] * tp_w1[(64 + k) * 64 + c];
    }
    g_pre_ox[b * 64 + c] = a;
    g_pre_tp[b * 64 + c] = t;
}

// ---------------- K1: per-batch top-1000 selection (bitonic sort of 2048 keys) ----------------
__global__ void __launch_bounds__(1024) select_kernel(const float* __restrict__ osm) {
    __shared__ u64 s[2048];
    int b = blockIdx.x, t = threadIdx.x;
#pragma unroll
    for (int m = t; m < 2048; m += 1024) {
        u64 key;
        if (m < 2000) {
            float x = osm[(b * 2000 + m) * 4];
            float y = osm[(b * 2000 + m) * 4 + 1];
            float d2 = x * x + y * y;
            key = ((u64)__float_as_uint(d2) << 32) | (u32)m;
        } else {
            key = ~0ull;
        }
        s[m] = key;
    }
    __syncthreads();
    for (int k = 2; k <= 2048; k <<= 1) {
        for (int j = k >> 1; j > 0; j >>= 1) {
            int i0 = ((t & ~(j - 1)) << 1) | (t & (j - 1));
            int i1 = i0 | j;
            bool up = ((i0 & k) == 0);
            u64 A = s[i0], B = s[i1];
            if ((A > B) == up) { s[i0] = B; s[i1] = A; }
            __syncthreads();
        }
    }
    if (t < 1000) {
        u32 m = (u32)(s[t] & 0xffffffffull);
        g_pts[(b * 1000 + t) * 2]     = osm[(b * 2000 + m) * 4];
        g_pts[(b * 1000 + t) * 2 + 1] = osm[(b * 2000 + m) * 4 + 1];
    }
}

// ---------------- K2: per-point MLP (lane = point) ----------------
__global__ void __launch_bounds__(128) mlp_kernel(
    const float* __restrict__ ox_w1, const float* __restrict__ ox_g1, const float* __restrict__ ox_be1,
    const float* __restrict__ ox_w2, const float* __restrict__ ox_b2,
    const float* __restrict__ tp_w1, const float* __restrict__ tp_g1, const float* __restrict__ tp_be1,
    const float* __restrict__ tp_w2, const float* __restrict__ tp_b2,
    const float* __restrict__ tp_g2, const float* __restrict__ tp_be2,
    const float* __restrict__ tp_w3, const float* __restrict__ tp_b3,
    const float* __restrict__ end) {
    __shared__ float s_pre_ox[64], s_pre_tp[64];
    __shared__ float s_oxx[64], s_oxy[64], s_tpx[64], s_tpy[64];
    __shared__ float s_oxg[64], s_oxbe[64], s_g1[64], s_be1[64], s_g2[64], s_be2[64], s_b2[64];
    __shared__ float s_oxw2[128], s_w3[128];
    __shared__ __align__(16) float s_w2[64 * 64];
    __shared__ float s_red[128];

    int b = blockIdx.y;
    int tid = threadIdx.x;

    if (tid < 64) {
        s_pre_ox[tid] = g_pre_ox[b * 64 + tid];
        s_pre_tp[tid] = g_pre_tp[b * 64 + tid];
        s_oxx[tid] = ox_w1[128 * 64 + tid];
        s_oxy[tid] = ox_w1[129 * 64 + tid];
        s_tpx[tid] = tp_w1[128 * 64 + tid];
        s_tpy[tid] = tp_w1[129 * 64 + tid];
        s_oxg[tid] = ox_g1[tid];  s_oxbe[tid] = ox_be1[tid];
        s_g1[tid]  = tp_g1[tid];  s_be1[tid]  = tp_be1[tid];
        s_g2[tid]  = tp_g2[tid];  s_be2[tid]  = tp_be2[tid];
        s_b2[tid]  = tp_b2[tid];
    }
    s_oxw2[tid] = ox_w2[tid];
    s_w3[tid]   = tp_w3[tid];
#pragma unroll
    for (int i = tid; i < 4096; i += 128) s_w2[i] = tp_w2[i];
    __syncthreads();

    int i = blockIdx.x * 128 + tid;
    bool act = i < 1000;
    float x = 0.f, y = 0.f;
    if (act) {
        x = g_pts[(b * 1000 + i) * 2];
        y = g_pts[(b * 1000 + i) * 2 + 1];
    }

    float h[64];
    // offset net, layer 1
#pragma unroll
    for (int c = 0; c < 64; c++) h[c] = s_pre_ox[c] + x * s_oxx[c] + y * s_oxy[c];
    ln_gelu(h, s_oxg, s_oxbe);
    // offset net, layer 2 (64 -> 2)
    float o0 = ox_b2[0], o1 = ox_b2[1];
#pragma unroll
    for (int c = 0; c < 64; c++) { o0 += h[c] * s_oxw2[2 * c]; o1 += h[c] * s_oxw2[2 * c + 1]; }
    float tx = x + o0, ty = y + o1;

    // target net, layer 1
#pragma unroll
    for (int c = 0; c < 64; c++) h[c] = s_pre_tp[c] + tx * s_tpx[c] + ty * s_tpy[c];
    ln_gelu(h, s_g1, s_be1);

    // target net, layer 2: 64x64 GEMV per point, packed f32x2
    float h3[64];
    const u64* w2p = (const u64*)s_w2;
#pragma unroll
    for (int jc = 0; jc < 4; jc++) {
        u64 acc[8];
#pragma unroll
        for (int j = 0; j < 8; j++) acc[j] = pack2(s_b2[jc * 16 + 2 * j], s_b2[jc * 16 + 2 * j + 1]);
#pragma unroll
        for (int k = 0; k < 64; k++) {
            u64 hk = pack2(h[k], h[k]);
#pragma unroll
            for (int j = 0; j < 8; j++) acc[j] = fma2(hk, w2p[k * 32 + jc * 8 + j], acc[j]);
        }
#pragma unroll
        for (int j = 0; j < 8; j++) {
            float lo, hi; unpack2(acc[j], lo, hi);
            h3[jc * 16 + 2 * j] = lo; h3[jc * 16 + 2 * j + 1] = hi;
        }
    }
    ln_gelu(h3, s_g2, s_be2);

    // target net, layer 3 (64 -> 2)
    float t0 = tp_b3[0], t1 = tp_b3[1];
#pragma unroll
    for (int c = 0; c < 64; c++) { t0 += h3[c] * s_w3[2 * c]; t1 += h3[c] * s_w3[2 * c + 1]; }

    if (act) {
        g_targets[(b * 1000 + i) * 2]     = t0;
        g_targets[(b * 1000 + i) * 2 + 1] = t1;
    }

    // smooth-L1 partial vs end
    float e0 = end[2 * b], e1 = end[2 * b + 1];
    float sm = act ? (sl1(t0 - e0) + sl1(t1 - e1)) : 0.f;
    s_red[tid] = sm;
    __syncthreads();
#pragma unroll
    for (int s = 64; s > 0; s >>= 1) {
        if (tid < s) s_red[tid] += s_red[tid + s];
        __syncthreads();
    }
    if (tid == 0) g_off_part[b * 8 + blockIdx.x] = s_red[0];
}

// ---------------- K3: per-batch stats, policy, top-50 ----------------
__global__ void __launch_bounds__(256) finalize_kernel(const float* __restrict__ end,
                                                       float* __restrict__ out) {
    __shared__ float s_t[2000];
    __shared__ float s_pd[1024];
    __shared__ u64 s_key[1024];
    __shared__ float s_r[256];
    __shared__ int s_ri[256];

    int b = blockIdx.x, tid = threadIdx.x;
    for (int i = tid; i < 2000; i += 256) s_t[i] = g_targets[b * 2000 + i];
    __syncthreads();

    // mean (sum / 1000)
    float a0 = 0.f, a1 = 0.f;
    for (int i = tid; i < 1000; i += 256) { a0 += s_t[2 * i]; a1 += s_t[2 * i + 1]; }
    s_r[tid] = a0; __syncthreads();
    for (int s = 128; s > 0; s >>= 1) { if (tid < s) s_r[tid] += s_r[tid + s]; __syncthreads(); }
    float m0 = s_r[0] * 0.001f; __syncthreads();
    s_r[tid] = a1; __syncthreads();
    for (int s = 128; s > 0; s >>= 1) { if (tid < s) s_r[tid] += s_r[tid + s]; __syncthreads(); }
    float m1 = s_r[0] * 0.001f; __syncthreads();

    // var (ddof=1), two-pass
    float q0 = 0.f, q1 = 0.f;
    for (int i = tid; i < 1000; i += 256) {
        float d0 = s_t[2 * i] - m0, d1 = s_t[2 * i + 1] - m1;
        q0 += d0 * d0; q1 += d1 * d1;
    }
    s_r[tid] = q0; __syncthreads();
    for (int s = 128; s > 0; s >>= 1) { if (tid < s) s_r[tid] += s_r[tid + s]; __syncthreads(); }
    float v0 = s_r[0] / 999.0f; __syncthreads();
    s_r[tid] = q1; __syncthreads();
    for (int s = 128; s > 0; s >>= 1) { if (tid < s) s_r[tid] += s_r[tid + s]; __syncthreads(); }
    float v1 = s_r[0] / 999.0f; __syncthreads();

    // policy_dist (mirrors reference formula exactly)
    float den0 = sqrtf(6.2831853071795864f * v0 + 1e-6f);
    float den1 = sqrtf(6.2831853071795864f * v1 + 1e-6f);
    for (int i = tid; i < 1024; i += 256) {
        float pd = -1.0f;
        if (i < 1000) {
            float dx = s_t[2 * i] - m0, dy = s_t[2 * i + 1] - m1;
            float pdx = expf(-0.5f * dx * dx / v0 + 1e-6f) / den0;
            float pdy = expf(-0.5f * dy * dy / v1 + 1e-6f) / den1;
            pd = pdx * pdy;
        }
        s_pd[i] = pd;
    }
    __syncthreads();

    // logsumexp over pd
    float mx = -1.0f;
    for (int i = tid; i < 1000; i += 256) mx = fmaxf(mx, s_pd[i]);
    s_r[tid] = mx; __syncthreads();
    for (int s = 128; s > 0; s >>= 1) { if (tid < s) s_r[tid] = fmaxf(s_r[tid], s_r[tid + s]); __syncthreads(); }
    mx = s_r[0]; __syncthreads();
    float se = 0.f;
    for (int i = tid; i < 1000; i += 256) se += expf(s_pd[i] - mx);
    s_r[tid] = se; __syncthreads();
    for (int s = 128; s > 0; s >>= 1) { if (tid < s) s_r[tid] += s_r[tid + s]; __syncthreads(); }
    float lse = mx + logf(s_r[0]); __syncthreads();

    // argmin distance to end (first-index tiebreak) -> picked
    float e0 = end[2 * b], e1 = end[2 * b + 1];
    float bd = 3.4e38f; int bi = 0x7fffffff;
    for (int i = tid; i < 1000; i += 256) {
        float dx = g_pts[(b * 1000 + i) * 2] - e0;
        float dy = g_pts[(b * 1000 + i) * 2 + 1] - e1;
        float ds = sqrtf(dx * dx + dy * dy);
        if (ds < bd || (ds == bd && i < bi)) { bd = ds; bi = i; }
    }
    s_r[tid] = bd; s_ri[tid] = bi; __syncthreads();
    for (int s = 128; s > 0; s >>= 1) {
        if (tid < s) {
            if (s_r[tid + s] < s_r[tid] || (s_r[tid + s] == s_r[tid] && s_ri[tid + s] < s_ri[tid])) {
                s_r[tid] = s_r[tid + s]; s_ri[tid] = s_ri[tid + s];
            }
        }
        __syncthreads();
    }
    float picked = s_pd[s_ri[0]];
    __syncthreads();

    // top-50 by pd descending, stable on index (bitonic over packed keys)
    for (int i = tid; i < 1024; i += 256) {
        u32 pb = (i < 1000) ? __float_as_uint(s_pd[i]) : 0u;
        s_key[i] = ((u64)(0xFFFFFFFFu - pb) << 32) | (u32)i;
    }
    __syncthreads();
    for (int k = 2; k <= 1024; k <<= 1) {
        for (int j = k >> 1; j > 0; j >>= 1) {
#pragma unroll
            for (int p = 0; p < 2; p++) {
                int t2 = tid + p * 256;
                int i0 = ((t2 & ~(j - 1)) << 1) | (t2 & (j - 1));
                int i1 = i0 | j;
                bool up = ((i0 & k) == 0);
                u64 A = s_key[i0], B = s_key[i1];
                if ((A > B) == up) { s_key[i0] = B; s_key[i1] = A; }
            }
            __syncthreads();
        }
    }

    float es = 0.f;
    if (tid < 50) {
        int id = (int)(u32)(s_key[tid] & 0xffffffffull);
        float t0 = s_t[2 * id], t1 = s_t[2 * id + 1];
        out[2 + (b * 50 + tid) * 2]     = t0;
        out[2 + (b * 50 + tid) * 2 + 1] = t1;
        es = sl1(t0 - e0) + sl1(t1 - e1);
    }
    s_r[tid] = es; __syncthreads();
    for (int s = 128; s > 0; s >>= 1) { if (tid < s) s_r[tid] += s_r[tid + s]; __syncthreads(); }
    if (tid == 0) {
        g_cls[b] = lse - picked;
        g_endsum[b] = s_r[0];
    }
}

// ---------------- K4: final scalar reductions ----------------
__global__ void __launch_bounds__(512) reduce_kernel(float* __restrict__ out) {
    __shared__ float r[512];
    int tid = threadIdx.x;
    float offs = 0.f;
    for (int i = tid; i < 4096; i += 512) offs += g_off_part[i];
    float cls = g_cls[tid];
    float ends = g_endsum[tid];

    r[tid] = offs; __syncthreads();
    for (int s = 256; s > 0; s >>= 1) { if (tid < s) r[tid] += r[tid + s]; __syncthreads(); }
    float offT = r[0]; __syncthreads();
    r[tid] = cls; __syncthreads();
    for (int s = 256; s > 0; s >>= 1) { if (tid < s) r[tid] += r[tid + s]; __syncthreads(); }
    float clsT = r[0]; __syncthreads();
    r[tid] = ends; __syncthreads();
    for (int s = 256; s > 0; s >>= 1) { if (tid < s) r[tid] += r[tid + s]; __syncthreads(); }
    float endT = r[0];

    if (tid == 0) {
        out[0] = clsT / 512.0f;                                    // L_cls
        out[1] = offT / 1024000.0f + 3.0f * (endT / 51200.0f);     // L_off + 3*L_end
    }
}

extern "C" void kernel_launch(void* const* d_in, const int* in_sizes, int n_in,
                              void* d_out, int out_size) {
    const float* osm   = (const float*)d_in[0];
    const float* at    = (const float*)d_in[1];
    const float* vf    = (const float*)d_in[2];
    const float* end   = (const float*)d_in[3];
    // d_in[4] = speed (unused)
    const float* ox_w1 = (const float*)d_in[5];
    const float* ox_b1 = (const float*)d_in[6];
    const float* ox_g1 = (const float*)d_in[7];
    const float* ox_be1= (const float*)d_in[8];
    const float* ox_w2 = (const float*)d_in[9];
    const float* ox_b2 = (const float*)d_in[10];
    const float* tp_w1 = (const float*)d_in[11];
    const float* tp_b1 = (const float*)d_in[12];
    const float* tp_g1 = (const float*)d_in[13];
    const float* tp_be1= (const float*)d_in[14];
    const float* tp_w2 = (const float*)d_in[15];
    const float* tp_b2 = (const float*)d_in[16];
    const float* tp_g2 = (const float*)d_in[17];
    const float* tp_be2= (const float*)d_in[18];
    const float* tp_w3 = (const float*)d_in[19];
    const float* tp_b3 = (const float*)d_in[20];
    float* out = (float*)d_out;

    precompute_kernel<<<512, 64>>>(at, vf, ox_w1, ox_b1, tp_w1, tp_b1);
    select_kernel<<<512, 1024>>>(osm);
    dim3 g(8, 512);
    mlp_kernel<<<g, 128>>>(ox_w1, ox_g1, ox_be1, ox_w2, ox_b2,
                           tp_w1, tp_g1, tp_be1, tp_w2, tp_b2,
                           tp_g2, tp_be2, tp_w3, tp_b3, end);
    finalize_kernel<<<512, 256>>>(end, out);
    reduce_kernel<<<1, 512>>>(out);
}

// round 2
// speedup vs baseline: 1.2915x; 1.2915x over previous
#include <cuda_runtime.h>
#include <cuda_bf16.h>
#include <cstdint>

typedef unsigned long long u64;
typedef unsigned int u32;

// ---------------- scratch (no allocations allowed) ----------------
__device__ float g_pre_ox[512 * 64];
__device__ float g_pre_tp[512 * 64];
__device__ float g_pts[512 * 1000 * 2];
__device__ float g_targets[512 * 1000 * 2];
__device__ float g_off_part[512 * 4];
__device__ float g_cls[512];
__device__ float g_endsum[512];

__device__ __forceinline__ float sl1(float z) {
    float d = fabsf(z);
    return d < 1.0f ? 0.5f * d * d : d - 0.5f;
}

__device__ __forceinline__ float gelu(float z) {
    return z * ((erff(z * 0.70710678118654752f) + 1.0f) * 0.5f);
}

// tf32 round (result is f32 bit-pattern with low mantissa cleared)
__device__ __forceinline__ u32 tf32_rna(float x) {
    u32 r; asm("cvt.rna.tf32.f32 %0, %1;" : "=r"(r) : "f"(x)); return r;
}

// m16n8k8 tf32 MMA, D += A*B
__device__ __forceinline__ void mma8(float* c, const u32* a, u32 b0, u32 b1) {
    asm volatile(
        "mma.sync.aligned.m16n8k8.row.col.f32.tf32.tf32.f32 "
        "{%0,%1,%2,%3},{%4,%5,%6,%7},{%8,%9},{%0,%1,%2,%3};"
        : "+f"(c[0]), "+f"(c[1]), "+f"(c[2]), "+f"(c[3])
        : "r"(a[0]), "r"(a[1]), "r"(a[2]), "r"(a[3]), "r"(b0), "r"(b1));
}

// LayerNorm (eps 1e-5) + exact GELU, in registers (lane = point)
__device__ __forceinline__ void ln_gelu(float* h, const float* g, const float* be) {
    float m = 0.f;
#pragma unroll
    for (int c = 0; c < 64; c++) m += h[c];
    m *= 0.015625f;
    float v = 0.f;
#pragma unroll
    for (int c = 0; c < 64; c++) { float d = h[c] - m; v += d * d; }
    v *= 0.015625f;
    float r = rsqrtf(v + 1e-5f);
#pragma unroll
    for (int c = 0; c < 64; c++) {
        float z = (h[c] - m) * r * g[c] + be[c];
        h[c] = gelu(z);
    }
}

// ---------------- K0: per-batch precompute of feat@W1 constant part ----------------
__global__ void precompute_kernel(const float* __restrict__ at, const float* __restrict__ vf,
                                  const float* __restrict__ ox_w1, const float* __restrict__ ox_b1,
                                  const float* __restrict__ tp_w1, const float* __restrict__ tp_b1) {
    __shared__ float s_vf[64], s_at[64];
    int b = blockIdx.x, c = threadIdx.x;
    s_vf[c] = vf[b * 64 + c];
    s_at[c] = at[b * 64 + c];
    __syncthreads();
    float a = ox_b1[c], t = tp_b1[c];
#pragma unroll 8
    for (int k = 0; k < 64; k++) {
        a += s_vf[k] * ox_w1[k * 64 + c] + s_at[k] * ox_w1[(64 + k) * 64 + c];
        t += s_vf[k] * tp_w1[k * 64 + c] + s_at[k] * tp_w1[(64 + k) * 64 + c];
    }
    g_pre_ox[b * 64 + c] = a;
    g_pre_tp[b * 64 + c] = t;
}

// ---------------- K1: per-batch top-1000 selection (bitonic sort of 2048 keys) ----------------
// Stage distance j<=32: each warp's compare region is a private, fixed 64-element
// window [64w, 64w+64)  =>  __syncwarp suffices. Block barrier only for j>=64 and
// on big->small transitions.
__global__ void __launch_bounds__(1024) select_kernel(const float* __restrict__ osm) {
    __shared__ u64 s[2048];
    int b = blockIdx.x, t = threadIdx.x;
#pragma unroll
    for (int m = t; m < 2048; m += 1024) {
        u64 key;
        if (m < 2000) {
            float x = osm[(b * 2000 + m) * 4];
            float y = osm[(b * 2000 + m) * 4 + 1];
            float d2 = x * x + y * y;
            key = ((u64)__float_as_uint(d2) << 32) | (u32)m;
        } else {
            key = ~0ull;
        }
        s[m] = key;
    }
    bool lastBig = true;
    for (int k = 2; k <= 2048; k <<= 1) {
        for (int j = k >> 1; j > 0; j >>= 1) {
            bool big = (j >= 64);
            if (big || lastBig) __syncthreads(); else __syncwarp();
            int i0 = ((t & ~(j - 1)) << 1) | (t & (j - 1));
            int i1 = i0 | j;
            bool up = ((i0 & k) == 0);
            u64 A = s[i0], B = s[i1];
            if ((A > B) == up) { s[i0] = B; s[i1] = A; }
            lastBig = big;
        }
    }
    __syncthreads();
    if (t < 1000) {
        u32 m = (u32)(s[t] & 0xffffffffull);
        g_pts[(b * 1000 + t) * 2]     = osm[(b * 2000 + m) * 4];
        g_pts[(b * 1000 + t) * 2 + 1] = osm[(b * 2000 + m) * 4 + 1];
    }
}

// ---------------- K2: per-point MLP; 64x64 layer via tensor cores ----------------
// Block = 256 threads = 8 warps = 256 points.  Phase A: lane=point computes both
// layer-1s + LN/GELU in registers, stores h to padded smem.  Phase B: each warp
// does a 32x64 @ 64x64 tf32 MMA (3-term hi/lo split = fp32 accuracy), then LN +
// GELU + 64->2 in fragment layout with quad shuffles.
#define HSTRIDE 68
#define WSTRIDE 72
#define MLP_DSMEM ((256 * HSTRIDE + 2 * 64 * WSTRIDE) * 4)

__global__ void __launch_bounds__(256, 2) mlp_kernel(
    const float* __restrict__ ox_w1, const float* __restrict__ ox_g1, const float* __restrict__ ox_be1,
    const float* __restrict__ ox_w2, const float* __restrict__ ox_b2,
    const float* __restrict__ tp_w1, const float* __restrict__ tp_g1, const float* __restrict__ tp_be1,
    const float* __restrict__ tp_w2, const float* __restrict__ tp_b2,
    const float* __restrict__ tp_g2, const float* __restrict__ tp_be2,
    const float* __restrict__ tp_w3, const float* __restrict__ tp_b3,
    const float* __restrict__ end) {
    extern __shared__ float dsm[];
    float* hbuf = dsm;                       // [256][HSTRIDE]
    float* w2h  = dsm + 256 * HSTRIDE;       // [64][WSTRIDE] tf32-hi of tp_w2
    float* w2l  = w2h + 64 * WSTRIDE;        // [64][WSTRIDE] tf32-lo

    __shared__ float s_pre_ox[64], s_pre_tp[64];
    __shared__ float s_oxx[64], s_oxy[64], s_tpx[64], s_tpy[64];
    __shared__ float s_oxg[64], s_oxbe[64], s_g1[64], s_be1[64];
    __shared__ float s_g2[64], s_be2[64], s_b2[64];
    __shared__ float s_oxw2[128], s_w3[128];
    __shared__ float s_red[256];

    int b = blockIdx.y;
    int tid = threadIdx.x;

    if (tid < 64) {
        s_pre_ox[tid] = g_pre_ox[b * 64 + tid];
        s_pre_tp[tid] = g_pre_tp[b * 64 + tid];
        s_oxx[tid] = ox_w1[128 * 64 + tid];
        s_oxy[tid] = ox_w1[129 * 64 + tid];
        s_tpx[tid] = tp_w1[128 * 64 + tid];
        s_tpy[tid] = tp_w1[129 * 64 + tid];
        s_oxg[tid] = ox_g1[tid];  s_oxbe[tid] = ox_be1[tid];
        s_g1[tid]  = tp_g1[tid];  s_be1[tid]  = tp_be1[tid];
        s_g2[tid]  = tp_g2[tid];  s_be2[tid]  = tp_be2[tid];
        s_b2[tid]  = tp_b2[tid];
    }
    if (tid < 128) { s_oxw2[tid] = ox_w2[tid]; s_w3[tid] = tp_w3[tid]; }
    // split tp_w2 into tf32 hi/lo in smem
    for (int i = tid; i < 4096; i += 256) {
        float w = tp_w2[i];
        u32 hb = tf32_rna(w);
        float lo = w - __uint_as_float(hb);
        u32 lb = tf32_rna(lo);
        w2h[(i >> 6) * WSTRIDE + (i & 63)] = __uint_as_float(hb);
        w2l[(i >> 6) * WSTRIDE + (i & 63)] = __uint_as_float(lb);
    }
    __syncthreads();

    // ---------- Phase A: lane = point ----------
    int i = blockIdx.x * 256 + tid;
    bool act = i < 1000;
    float x = 0.f, y = 0.f;
    if (act) {
        x = g_pts[(b * 1000 + i) * 2];
        y = g_pts[(b * 1000 + i) * 2 + 1];
    }

    float h[64];
#pragma unroll
    for (int c = 0; c < 64; c++) h[c] = s_pre_ox[c] + x * s_oxx[c] + y * s_oxy[c];
    ln_gelu(h, s_oxg, s_oxbe);
    float o0 = ox_b2[0], o1 = ox_b2[1];
#pragma unroll
    for (int c = 0; c < 64; c++) { o0 += h[c] * s_oxw2[2 * c]; o1 += h[c] * s_oxw2[2 * c + 1]; }
    float tx = x + o0, ty = y + o1;

#pragma unroll
    for (int c = 0; c < 64; c++) h[c] = s_pre_tp[c] + tx * s_tpx[c] + ty * s_tpy[c];
    ln_gelu(h, s_g1, s_be1);

    // store h to padded smem (STS.128, conflict-free: stride 68 words)
#pragma unroll
    for (int c = 0; c < 16; c++) {
        float4 v = make_float4(h[4 * c], h[4 * c + 1], h[4 * c + 2], h[4 * c + 3]);
        *reinterpret_cast<float4*>(&hbuf[tid * HSTRIDE + 4 * c]) = v;
    }
    __syncthreads();

    // ---------- Phase B: warp GEMM + fragment epilogue ----------
    int wid = tid >> 5;
    int lane = tid & 31;
    int gid = lane >> 2, tig = lane & 3;
    float b3_0 = tp_b3[0], b3_1 = tp_b3[1];
    float e0 = end[2 * b], e1 = end[2 * b + 1];
    float smAcc = 0.f;

#pragma unroll
    for (int mt = 0; mt < 2; mt++) {
        int r0 = wid * 32 + mt * 16 + gid;      // row of c0/c1 ; r0+8 for c2/c3
        float cst[8][4];
#pragma unroll
        for (int nt = 0; nt < 8; nt++)
#pragma unroll
            for (int q = 0; q < 4; q++) cst[nt][q] = 0.f;

#pragma unroll
        for (int kt = 0; kt < 8; kt++) {
            int kc = kt * 8 + tig;
            float a0 = hbuf[r0 * HSTRIDE + kc];
            float a1 = hbuf[(r0 + 8) * HSTRIDE + kc];
            float a2 = hbuf[r0 * HSTRIDE + kc + 4];
            float a3 = hbuf[(r0 + 8) * HSTRIDE + kc + 4];
            u32 ah[4], al[4];
            ah[0] = tf32_rna(a0); al[0] = tf32_rna(a0 - __uint_as_float(ah[0]));
            ah[1] = tf32_rna(a1); al[1] = tf32_rna(a1 - __uint_as_float(ah[1]));
            ah[2] = tf32_rna(a2); al[2] = tf32_rna(a2 - __uint_as_float(ah[2]));
            ah[3] = tf32_rna(a3); al[3] = tf32_rna(a3 - __uint_as_float(ah[3]));
#pragma unroll
            for (int nt = 0; nt < 8; nt++) {
                int nc = nt * 8 + gid;
                u32 bh0 = __float_as_uint(w2h[kc * WSTRIDE + nc]);
                u32 bh1 = __float_as_uint(w2h[(kc + 4) * WSTRIDE + nc]);
                u32 bl0 = __float_as_uint(w2l[kc * WSTRIDE + nc]);
                u32 bl1 = __float_as_uint(w2l[(kc + 4) * WSTRIDE + nc]);
                mma8(cst[nt], ah, bh0, bh1);
                mma8(cst[nt], ah, bl0, bl1);
                mma8(cst[nt], al, bh0, bh1);
            }
        }

        // epilogue: +bias, LN (quad shuffles), GELU, 64->2
        float sA = 0.f, sB = 0.f;
#pragma unroll
        for (int nt = 0; nt < 8; nt++) {
            int col0 = nt * 8 + 2 * tig, col1 = col0 + 1;
            cst[nt][0] += s_b2[col0]; cst[nt][1] += s_b2[col1];
            cst[nt][2] += s_b2[col0]; cst[nt][3] += s_b2[col1];
            sA += cst[nt][0] + cst[nt][1];
            sB += cst[nt][2] + cst[nt][3];
        }
        sA += __shfl_xor_sync(0xffffffffu, sA, 1); sA += __shfl_xor_sync(0xffffffffu, sA, 2);
        sB += __shfl_xor_sync(0xffffffffu, sB, 1); sB += __shfl_xor_sync(0xffffffffu, sB, 2);
        float mA = sA * 0.015625f, mB = sB * 0.015625f;
        float qA = 0.f, qB = 0.f;
#pragma unroll
        for (int nt = 0; nt < 8; nt++) {
            float d0 = cst[nt][0] - mA, d1 = cst[nt][1] - mA;
            float d2 = cst[nt][2] - mB, d3 = cst[nt][3] - mB;
            qA += d0 * d0 + d1 * d1;
            qB += d2 * d2 + d3 * d3;
        }
        qA += __shfl_xor_sync(0xffffffffu, qA, 1); qA += __shfl_xor_sync(0xffffffffu, qA, 2);
        qB += __shfl_xor_sync(0xffffffffu, qB, 1); qB += __shfl_xor_sync(0xffffffffu, qB, 2);
        float rA = rsqrtf(qA * 0.015625f + 1e-5f);
        float rB = rsqrtf(qB * 0.015625f + 1e-5f);

        float pA0 = 0.f, pA1 = 0.f, pB0 = 0.f, pB1 = 0.f;
#pragma unroll
        for (int nt = 0; nt < 8; nt++) {
            int col0 = nt * 8 + 2 * tig, col1 = col0 + 1;
            float z;
            z = gelu((cst[nt][0] - mA) * rA * s_g2[col0] + s_be2[col0]);
            pA0 += z * s_w3[2 * col0]; pA1 += z * s_w3[2 * col0 + 1];
            z = gelu((cst[nt][1] - mA) * rA * s_g2[col1] + s_be2[col1]);
            pA0 += z * s_w3[2 * col1]; pA1 += z * s_w3[2 * col1 + 1];
            z = gelu((cst[nt][2] - mB) * rB * s_g2[col0] + s_be2[col0]);
            pB0 += z * s_w3[2 * col0]; pB1 += z * s_w3[2 * col0 + 1];
            z = gelu((cst[nt][3] - mB) * rB * s_g2[col1] + s_be2[col1]);
            pB0 += z * s_w3[2 * col1]; pB1 += z * s_w3[2 * col1 + 1];
        }
        pA0 += __shfl_xor_sync(0xffffffffu, pA0, 1); pA0 += __shfl_xor_sync(0xffffffffu, pA0, 2);
        pA1 += __shfl_xor_sync(0xffffffffu, pA1, 1); pA1 += __shfl_xor_sync(0xffffffffu, pA1, 2);
        pB0 += __shfl_xor_sync(0xffffffffu, pB0, 1); pB0 += __shfl_xor_sync(0xffffffffu, pB0, 2);
        pB1 += __shfl_xor_sync(0xffffffffu, pB1, 1); pB1 += __shfl_xor_sync(0xffffffffu, pB1, 2);

        if (tig == 0) {
            int iA = blockIdx.x * 256 + r0;
            int iB = iA + 8;
            float tA0 = pA0 + b3_0, tA1 = pA1 + b3_1;
            float tB0 = pB0 + b3_0, tB1 = pB1 + b3_1;
            if (iA < 1000) {
                g_targets[(b * 1000 + iA) * 2]     = tA0;
                g_targets[(b * 1000 + iA) * 2 + 1] = tA1;
                smAcc += sl1(tA0 - e0) + sl1(tA1 - e1);
            }
            if (iB < 1000) {
                g_targets[(b * 1000 + iB) * 2]     = tB0;
                g_targets[(b * 1000 + iB) * 2 + 1] = tB1;
                smAcc += sl1(tB0 - e0) + sl1(tB1 - e1);
            }
        }
    }

    s_red[tid] = smAcc;
    __syncthreads();
#pragma unroll
    for (int s = 128; s > 0; s >>= 1) {
        if (tid < s) s_red[tid] += s_red[tid + s];
        __syncthreads();
    }
    if (tid == 0) g_off_part[b * 4 + blockIdx.x] = s_red[0];
}

// ---------------- K3: per-batch stats, policy, top-50 ----------------
__global__ void __launch_bounds__(512) finalize_kernel(const float* __restrict__ end,
                                                       float* __restrict__ out) {
    __shared__ float s_t[2000];
    __shared__ float s_pd[1024];
    __shared__ u64 s_key[1024];
    __shared__ float s_r[512];
    __shared__ int s_ri[512];

    int b = blockIdx.x, tid = threadIdx.x;
    for (int i = tid; i < 2000; i += 512) s_t[i] = g_targets[b * 2000 + i];
    __syncthreads();

    // mean
    float a0 = 0.f, a1 = 0.f;
    for (int i = tid; i < 1000; i += 512) { a0 += s_t[2 * i]; a1 += s_t[2 * i + 1]; }
    s_r[tid] = a0; __syncthreads();
    for (int s = 256; s > 0; s >>= 1) { if (tid < s) s_r[tid] += s_r[tid + s]; __syncthreads(); }
    float m0 = s_r[0] * 0.001f; __syncthreads();
    s_r[tid] = a1; __syncthreads();
    for (int s = 256; s > 0; s >>= 1) { if (tid < s) s_r[tid] += s_r[tid + s]; __syncthreads(); }
    float m1 = s_r[0] * 0.001f; __syncthreads();

    // var (ddof=1), two-pass
    float q0 = 0.f, q1 = 0.f;
    for (int i = tid; i < 1000; i += 512) {
        float d0 = s_t[2 * i] - m0, d1 = s_t[2 * i + 1] - m1;
        q0 += d0 * d0; q1 += d1 * d1;
    }
    s_r[tid] = q0; __syncthreads();
    for (int s = 256; s > 0; s >>= 1) { if (tid < s) s_r[tid] += s_r[tid + s]; __syncthreads(); }
    float v0 = s_r[0] / 999.0f; __syncthreads();
    s_r[tid] = q1; __syncthreads();
    for (int s = 256; s > 0; s >>= 1) { if (tid < s) s_r[tid] += s_r[tid + s]; __syncthreads(); }
    float v1 = s_r[0] / 999.0f; __syncthreads();

    // policy_dist
    float den0 = sqrtf(6.2831853071795864f * v0 + 1e-6f);
    float den1 = sqrtf(6.2831853071795864f * v1 + 1e-6f);
    for (int i = tid; i < 1024; i += 512) {
        float pd = -1.0f;
        if (i < 1000) {
            float dx = s_t[2 * i] - m0, dy = s_t[2 * i + 1] - m1;
            float pdx = expf(-0.5f * dx * dx / v0 + 1e-6f) / den0;
            float pdy = expf(-0.5f * dy * dy / v1 + 1e-6f) / den1;
            pd = pdx * pdy;
        }
        s_pd[i] = pd;
    }
    __syncthreads();

    // logsumexp
    float mx = -1.0f;
    for (int i = tid; i < 1000; i += 512) mx = fmaxf(mx, s_pd[i]);
    s_r[tid] = mx; __syncthreads();
    for (int s = 256; s > 0; s >>= 1) { if (tid < s) s_r[tid] = fmaxf(s_r[tid], s_r[tid + s]); __syncthreads(); }
    mx = s_r[0]; __syncthreads();
    float se = 0.f;
    for (int i = tid; i < 1000; i += 512) se += expf(s_pd[i] - mx);
    s_r[tid] = se; __syncthreads();
    for (int s = 256; s > 0; s >>= 1) { if (tid < s) s_r[tid] += s_r[tid + s]; __syncthreads(); }
    float lse = mx + logf(s_r[0]); __syncthreads();

    // argmin distance to end (first-index tiebreak)
    float e0 = end[2 * b], e1 = end[2 * b + 1];
    float bd = 3.4e38f; int bi = 0x7fffffff;
    for (int i = tid; i < 1000; i += 512) {
        float dx = g_pts[(b * 1000 + i) * 2] - e0;
        float dy = g_pts[(b * 1000 + i) * 2 + 1] - e1;
        float ds = sqrtf(dx * dx + dy * dy);
        if (ds < bd || (ds == bd && i < bi)) { bd = ds; bi = i; }
    }
    s_r[tid] = bd; s_ri[tid] = bi; __syncthreads();
    for (int s = 256; s > 0; s >>= 1) {
        if (tid < s) {
            if (s_r[tid + s] < s_r[tid] || (s_r[tid + s] == s_r[tid] && s_ri[tid + s] < s_ri[tid])) {
                s_r[tid] = s_r[tid + s]; s_ri[tid] = s_ri[tid + s];
            }
        }
        __syncthreads();
    }
    float picked = s_pd[s_ri[0]];
    __syncthreads();

    // top-50 by pd desc, stable by index (bitonic, warp-local stages use syncwarp)
    for (int i = tid; i < 1024; i += 512) {
        u32 pb = (i < 1000) ? __float_as_uint(s_pd[i]) : 0u;
        s_key[i] = ((u64)(0xFFFFFFFFu - pb) << 32) | (u32)i;
    }
    bool lastBig = true;
    for (int k = 2; k <= 1024; k <<= 1) {
        for (int j = k >> 1; j > 0; j >>= 1) {
            bool big = (j >= 64);
            if (big || lastBig) __syncthreads(); else __syncwarp();
            int i0 = ((tid & ~(j - 1)) << 1) | (tid & (j - 1));
            int i1 = i0 | j;
            bool up = ((i0 & k) == 0);
            u64 A = s_key[i0], B = s_key[i1];
            if ((A > B) == up) { s_key[i0] = B; s_key[i1] = A; }
            lastBig = big;
        }
    }
    __syncthreads();

    float es = 0.f;
    if (tid < 50) {
        int id = (int)(u32)(s_key[tid] & 0xffffffffull);
        float t0 = s_t[2 * id], t1 = s_t[2 * id + 1];
        out[2 + (b * 50 + tid) * 2]     = t0;
        out[2 + (b * 50 + tid) * 2 + 1] = t1;
        es = sl1(t0 - e0) + sl1(t1 - e1);
    }
    s_r[tid] = es; __syncthreads();
    for (int s = 256; s > 0; s >>= 1) { if (tid < s) s_r[tid] += s_r[tid + s]; __syncthreads(); }
    if (tid == 0) {
        g_cls[b] = lse - picked;
        g_endsum[b] = s_r[0];
    }
}

// ---------------- K4: final scalar reductions ----------------
__global__ void __launch_bounds__(512) reduce_kernel(float* __restrict__ out) {
    __shared__ float r[512];
    int tid = threadIdx.x;
    float offs = 0.f;
    for (int i = tid; i < 2048; i += 512) offs += g_off_part[i];
    float cls = g_cls[tid];
    float ends = g_endsum[tid];

    r[tid] = offs; __syncthreads();
    for (int s = 256; s > 0; s >>= 1) { if (tid < s) r[tid] += r[tid + s]; __syncthreads(); }
    float offT = r[0]; __syncthreads();
    r[tid] = cls; __syncthreads();
    for (int s = 256; s > 0; s >>= 1) { if (tid < s) r[tid] += r[tid + s]; __syncthreads(); }
    float clsT = r[0]; __syncthreads();
    r[tid] = ends; __syncthreads();
    for (int s = 256; s > 0; s >>= 1) { if (tid < s) r[tid] += r[tid + s]; __syncthreads(); }
    float endT = r[0];

    if (tid == 0) {
        out[0] = clsT / 512.0f;
        out[1] = offT / 1024000.0f + 3.0f * (endT / 51200.0f);
    }
}

extern "C" void kernel_launch(void* const* d_in, const int* in_sizes, int n_in,
                              void* d_out, int out_size) {
    const float* osm   = (const float*)d_in[0];
    const float* at    = (const float*)d_in[1];
    const float* vf    = (const float*)d_in[2];
    const float* end   = (const float*)d_in[3];
    // d_in[4] = speed (unused)
    const float* ox_w1 = (const float*)d_in[5];
    const float* ox_b1 = (const float*)d_in[6];
    const float* ox_g1 = (const float*)d_in[7];
    const float* ox_be1= (const float*)d_in[8];
    const float* ox_w2 = (const float*)d_in[9];
    const float* ox_b2 = (const float*)d_in[10];
    const float* tp_w1 = (const float*)d_in[11];
    const float* tp_b1 = (const float*)d_in[12];
    const float* tp_g1 = (const float*)d_in[13];
    const float* tp_be1= (const float*)d_in[14];
    const float* tp_w2 = (const float*)d_in[15];
    const float* tp_b2 = (const float*)d_in[16];
    const float* tp_g2 = (const float*)d_in[17];
    const float* tp_be2= (const float*)d_in[18];
    const float* tp_w3 = (const float*)d_in[19];
    const float* tp_b3 = (const float*)d_in[20];
    float* out = (float*)d_out;

    cudaFuncSetAttribute(mlp_kernel, cudaFuncAttributeMaxDynamicSharedMemorySize, MLP_DSMEM);

    precompute_kernel<<<512, 64>>>(at, vf, ox_w1, ox_b1, tp_w1, tp_b1);
    select_kernel<<<512, 1024>>>(osm);
    dim3 g(4, 512);
    mlp_kernel<<<g, 256, MLP_DSMEM>>>(ox_w1, ox_g1, ox_be1, ox_w2, ox_b2,
                                      tp_w1, tp_g1, tp_be1, tp_w2, tp_b2,
                                      tp_g2, tp_be2, tp_w3, tp_b3, end);
    finalize_kernel<<<512, 512>>>(end, out);
    reduce_kernel<<<1, 512>>>(out);
}

// round 4
// speedup vs baseline: 1.4395x; 1.1146x over previous
#include <cuda_runtime.h>
#include <cuda_bf16.h>
#include <cstdint>

typedef unsigned long long u64;
typedef unsigned int u32;

// ---------------- scratch ----------------
__device__ float g_pre_ox[512 * 64];
__device__ float g_pre_tp[512 * 64];
__device__ float g_pts[512 * 1000 * 2];
__device__ float g_targets[512 * 1000 * 2];
__device__ float g_off_part[512 * 4];
__device__ float g_cls[512];
__device__ float g_endsum[512];

// ---------------- packed f32x2 helpers (FFMA2 path, PTX-only) ----------------
__device__ __forceinline__ u64 F2(float a, float b) {
    u64 r; asm("mov.b64 %0,{%1,%2};" : "=l"(r) : "f"(a), "f"(b)); return r;
}
__device__ __forceinline__ void UNPK(u64 v, float& a, float& b) {
    asm("mov.b64 {%0,%1},%2;" : "=f"(a), "=f"(b) : "l"(v));
}
__device__ __forceinline__ u64 FMA2(u64 a, u64 b, u64 c) {
    u64 d; asm("fma.rn.f32x2 %0,%1,%2,%3;" : "=l"(d) : "l"(a), "l"(b), "l"(c)); return d;
}
__device__ __forceinline__ u64 ADD2(u64 a, u64 b) {
    u64 d; asm("add.rn.f32x2 %0,%1,%2;" : "=l"(d) : "l"(a), "l"(b)); return d;
}
__device__ __forceinline__ u64 MUL2(u64 a, u64 b) {
    u64 d; asm("mul.rn.f32x2 %0,%1,%2;" : "=l"(d) : "l"(a), "l"(b)); return d;
}
__device__ __forceinline__ u64 LD2(const float* p) {
    return *reinterpret_cast<const u64*>(p);
}

__device__ __forceinline__ float sl1(float z) {
    float d = fabsf(z);
    return d < 1.0f ? 0.5f * d * d : d - 0.5f;
}

// Branchless exact-GELU: A&S 7.1.26 erfc approx (|err|<=1.5e-7 on erf).
// gelu(z) = relu(z) - 0.5*|z|*erfc(|z|/sqrt(2))
__device__ __forceinline__ float fast_gelu(float z) {
    float az = fabsf(z);
    float u = 0.70710678118654752f * az;
    float t;
    asm("rcp.approx.f32 %0, %1;" : "=f"(t) : "f"(fmaf(0.3275911f, u, 1.0f)));
    float e;
    asm("ex2.approx.f32 %0, %1;" : "=f"(e) : "f"(u * u * -1.4426950408889634f));
    float p = fmaf(1.061405429f, t, -1.453152027f);
    p = fmaf(p, t, 1.421413741f);
    p = fmaf(p, t, -0.284496736f);
    p = fmaf(p, t, 0.254829592f);
    float q = p * t * e;                 // erfc(u), u>=0
    return fmaf(-0.5f * az, q, fmaxf(z, 0.0f));
}

// tf32 round
__device__ __forceinline__ u32 tf32_rna(float x) {
    u32 r; asm("cvt.rna.tf32.f32 %0, %1;" : "=r"(r) : "f"(x)); return r;
}
// m16n8k8 tf32 MMA, D += A*B
__device__ __forceinline__ void mma8(float* c, const u32* a, u32 b0, u32 b1) {
    asm volatile(
        "mma.sync.aligned.m16n8k8.row.col.f32.tf32.tf32.f32 "
        "{%0,%1,%2,%3},{%4,%5,%6,%7},{%8,%9},{%0,%1,%2,%3};"
        : "+f"(c[0]), "+f"(c[1]), "+f"(c[2]), "+f"(c[3])
        : "r"(a[0]), "r"(a[1]), "r"(a[2]), "r"(a[3]), "r"(b0), "r"(b1));
}

// packed LayerNorm + GELU on 32 register pairs
__device__ __forceinline__ void ln_gelu_p(u64* h, const float* g, const float* be) {
    u64 s = h[0];
#pragma unroll
    for (int c = 1; c < 32; c++) s = ADD2(s, h[c]);
    float s0, s1; UNPK(s, s0, s1);
    float m = (s0 + s1) * 0.015625f;
    u64 mn = F2(-m, -m);
    u64 q = F2(0.f, 0.f);
#pragma unroll
    for (int c = 0; c < 32; c++) { h[c] = ADD2(h[c], mn); q = FMA2(h[c], h[c], q); }
    float q0, q1; UNPK(q, q0, q1);
    float r = rsqrtf((q0 + q1) * 0.015625f + 1e-5f);
    u64 rr = F2(r, r);
#pragma unroll
    for (int c = 0; c < 32; c++) {
        u64 z2 = FMA2(MUL2(h[c], rr), LD2(&g[2 * c]), LD2(&be[2 * c]));
        float z0, z1; UNPK(z2, z0, z1);
        h[c] = F2(fast_gelu(z0), fast_gelu(z1));
    }
}

__device__ __forceinline__ float wsum(float v) {
#pragma unroll
    for (int o = 16; o; o >>= 1) v += __shfl_xor_sync(0xffffffffu, v, o);
    return v;
}

// ---------------- K0: per-batch precompute (4-way k-split) ----------------
__global__ void __launch_bounds__(256) precompute_kernel(
    const float* __restrict__ at, const float* __restrict__ vf,
    const float* __restrict__ ox_w1, const float* __restrict__ ox_b1,
    const float* __restrict__ tp_w1, const float* __restrict__ tp_b1) {
    __shared__ float s_vf[64], s_at[64];
    __shared__ float pa[4][64], pt[4][64];
    int b = blockIdx.x, tid = threadIdx.x;
    int c = tid & 63, kq = tid >> 6;
    if (tid < 64) { s_vf[tid] = vf[b * 64 + tid]; s_at[tid] = at[b * 64 + tid]; }
    __syncthreads();
    float a = 0.f, t = 0.f;
#pragma unroll
    for (int k = kq * 16; k < kq * 16 + 16; k++) {
        a += s_vf[k] * ox_w1[k * 64 + c] + s_at[k] * ox_w1[(64 + k) * 64 + c];
        t += s_vf[k] * tp_w1[k * 64 + c] + s_at[k] * tp_w1[(64 + k) * 64 + c];
    }
    pa[kq][c] = a; pt[kq][c] = t;
    __syncthreads();
    if (tid < 64) {
        g_pre_ox[b * 64 + tid] = pa[0][tid] + pa[1][tid] + pa[2][tid] + pa[3][tid] + ox_b1[tid];
        g_pre_tp[b * 64 + tid] = pt[0][tid] + pt[1][tid] + pt[2][tid] + pt[3][tid] + tp_b1[tid];
    }
}

// ---------------- K1: top-1000 selection (bitonic 2048) ----------------
__global__ void __launch_bounds__(1024) select_kernel(const float* __restrict__ osm) {
    __shared__ u64 s[2048];
    int b = blockIdx.x, t = threadIdx.x;
#pragma unroll
    for (int m = t; m < 2048; m += 1024) {
        u64 key;
        if (m < 2000) {
            float x = osm[(b * 2000 + m) * 4];
            float y = osm[(b * 2000 + m) * 4 + 1];
            float d2 = x * x + y * y;
            key = ((u64)__float_as_uint(d2) << 32) | (u32)m;
        } else key = ~0ull;
        s[m] = key;
    }
    bool lastBig = true;
    for (int k = 2; k <= 2048; k <<= 1) {
        for (int j = k >> 1; j > 0; j >>= 1) {
            bool big = (j >= 64);
            if (big || lastBig) __syncthreads(); else __syncwarp();
            int i0 = ((t & ~(j - 1)) << 1) | (t & (j - 1));
            int i1 = i0 | j;
            bool up = ((i0 & k) == 0);
            u64 A = s[i0], B = s[i1];
            if ((A > B) == up) { s[i0] = B; s[i1] = A; }
            lastBig = big;
        }
    }
    __syncthreads();
    if (t < 1000) {
        u32 m = (u32)(s[t] & 0xffffffffull);
        g_pts[(b * 1000 + t) * 2]     = osm[(b * 2000 + m) * 4];
        g_pts[(b * 1000 + t) * 2 + 1] = osm[(b * 2000 + m) * 4 + 1];
    }
}

// ---------------- K2: per-point MLP ----------------
#define HSTRIDE 68
#define WSTRIDE 72
#define MLP_DSMEM ((256 * HSTRIDE + 2 * 64 * WSTRIDE) * 4)

__global__ void __launch_bounds__(256, 2) mlp_kernel(
    const float* __restrict__ ox_w1, const float* __restrict__ ox_g1, const float* __restrict__ ox_be1,
    const float* __restrict__ ox_w2, const float* __restrict__ ox_b2,
    const float* __restrict__ tp_w1, const float* __restrict__ tp_g1, const float* __restrict__ tp_be1,
    const float* __restrict__ tp_w2, const float* __restrict__ tp_b2,
    const float* __restrict__ tp_g2, const float* __restrict__ tp_be2,
    const float* __restrict__ tp_w3, const float* __restrict__ tp_b3,
    const float* __restrict__ end) {
    extern __shared__ float dsm[];
    float* hbuf = dsm;                       // [256][HSTRIDE]
    float* w2h  = dsm + 256 * HSTRIDE;       // [64][WSTRIDE]
    float* w2l  = w2h + 64 * WSTRIDE;

    __shared__ __align__(16) float s_pre_ox[64], s_pre_tp[64];
    __shared__ __align__(16) float s_oxx[64], s_oxy[64], s_tpx[64], s_tpy[64];
    __shared__ __align__(16) float s_oxg[64], s_oxbe[64], s_g1[64], s_be1[64];
    __shared__ __align__(16) float s_g2[64], s_be2[64], s_b2[64];
    __shared__ __align__(16) float s_oxw2a[64], s_oxw2b[64];
    __shared__ __align__(16) float s_w3[128];
    __shared__ float s_red[256];

    int b = blockIdx.y;
    int tid = threadIdx.x;

    if (tid < 64) {
        s_pre_ox[tid] = g_pre_ox[b * 64 + tid];
        s_pre_tp[tid] = g_pre_tp[b * 64 + tid];
        s_oxx[tid] = ox_w1[128 * 64 + tid];
        s_oxy[tid] = ox_w1[129 * 64 + tid];
        s_tpx[tid] = tp_w1[128 * 64 + tid];
        s_tpy[tid] = tp_w1[129 * 64 + tid];
        s_oxg[tid] = ox_g1[tid];  s_oxbe[tid] = ox_be1[tid];
        s_g1[tid]  = tp_g1[tid];  s_be1[tid]  = tp_be1[tid];
        s_g2[tid]  = tp_g2[tid];  s_be2[tid]  = tp_be2[tid];
        s_b2[tid]  = tp_b2[tid];
        s_oxw2a[tid] = ox_w2[2 * tid];
        s_oxw2b[tid] = ox_w2[2 * tid + 1];
    }
    if (tid < 128) s_w3[tid] = tp_w3[tid];
    for (int i = tid; i < 4096; i += 256) {
        float w = tp_w2[i];
        u32 hb = tf32_rna(w);
        float lo = w - __uint_as_float(hb);
        u32 lb = tf32_rna(lo);
        w2h[(i >> 6) * WSTRIDE + (i & 63)] = __uint_as_float(hb);
        w2l[(i >> 6) * WSTRIDE + (i & 63)] = __uint_as_float(lb);
    }
    __syncthreads();

    // ---------- Phase A: lane = point, packed f32x2 ----------
    int i = blockIdx.x * 256 + tid;
    bool act = i < 1000;
    float x = 0.f, y = 0.f;
    if (act) {
        x = g_pts[(b * 1000 + i) * 2];
        y = g_pts[(b * 1000 + i) * 2 + 1];
    }

    u64 h[32];
    {
        u64 xx = F2(x, x), yy = F2(y, y);
#pragma unroll
        for (int c = 0; c < 32; c++)
            h[c] = FMA2(yy, LD2(&s_oxy[2 * c]), FMA2(xx, LD2(&s_oxx[2 * c]), LD2(&s_pre_ox[2 * c])));
    }
    ln_gelu_p(h, s_oxg, s_oxbe);

    // offset head (deinterleaved weights => packed accumulators)
    float tx, ty;
    {
        u64 accA = F2(0.f, 0.f), accB = F2(0.f, 0.f);
#pragma unroll
        for (int c = 0; c < 32; c++) {
            accA = FMA2(h[c], LD2(&s_oxw2a[2 * c]), accA);
            accB = FMA2(h[c], LD2(&s_oxw2b[2 * c]), accB);
        }
        float a0, a1, b0, b1;
        UNPK(accA, a0, a1); UNPK(accB, b0, b1);
        tx = x + a0 + a1 + ox_b2[0];
        ty = y + b0 + b1 + ox_b2[1];
    }

    {
        u64 xx = F2(tx, tx), yy = F2(ty, ty);
#pragma unroll
        for (int c = 0; c < 32; c++)
            h[c] = FMA2(yy, LD2(&s_tpy[2 * c]), FMA2(xx, LD2(&s_tpx[2 * c]), LD2(&s_pre_tp[2 * c])));
    }
    ln_gelu_p(h, s_g1, s_be1);

    // store h (STS.128, conflict-free)
#pragma unroll
    for (int c = 0; c < 16; c++) {
        float a0, a1, b0, b1;
        UNPK(h[2 * c], a0, a1); UNPK(h[2 * c + 1], b0, b1);
        *reinterpret_cast<float4*>(&hbuf[tid * HSTRIDE + 4 * c]) = make_float4(a0, a1, b0, b1);
    }
    __syncthreads();

    // ---------- Phase B: warp GEMM (tf32 3-term) + fragment epilogue ----------
    int wid = tid >> 5;
    int lane = tid & 31;
    int gid = lane >> 2, tig = lane & 3;
    float b3_0 = tp_b3[0], b3_1 = tp_b3[1];
    float e0 = end[2 * b], e1 = end[2 * b + 1];
    float smAcc = 0.f;

#pragma unroll
    for (int mt = 0; mt < 2; mt++) {
        int r0 = wid * 32 + mt * 16 + gid;
        float cst[8][4];
#pragma unroll
        for (int nt = 0; nt < 8; nt++)
#pragma unroll
            for (int qq = 0; qq < 4; qq++) cst[nt][qq] = 0.f;

#pragma unroll
        for (int kt = 0; kt < 8; kt++) {
            int kc = kt * 8 + tig;
            float a0 = hbuf[r0 * HSTRIDE + kc];
            float a1 = hbuf[(r0 + 8) * HSTRIDE + kc];
            float a2 = hbuf[r0 * HSTRIDE + kc + 4];
            float a3 = hbuf[(r0 + 8) * HSTRIDE + kc + 4];
            u32 ah[4], al[4];
            ah[0] = tf32_rna(a0); al[0] = tf32_rna(a0 - __uint_as_float(ah[0]));
            ah[1] = tf32_rna(a1); al[1] = tf32_rna(a1 - __uint_as_float(ah[1]));
            ah[2] = tf32_rna(a2); al[2] = tf32_rna(a2 - __uint_as_float(ah[2]));
            ah[3] = tf32_rna(a3); al[3] = tf32_rna(a3 - __uint_as_float(ah[3]));
#pragma unroll
            for (int nt = 0; nt < 8; nt++) {
                int nc = nt * 8 + gid;
                u32 bh0 = __float_as_uint(w2h[kc * WSTRIDE + nc]);
                u32 bh1 = __float_as_uint(w2h[(kc + 4) * WSTRIDE + nc]);
                u32 bl0 = __float_as_uint(w2l[kc * WSTRIDE + nc]);
                u32 bl1 = __float_as_uint(w2l[(kc + 4) * WSTRIDE + nc]);
                mma8(cst[nt], ah, bh0, bh1);
                mma8(cst[nt], ah, bl0, bl1);
                mma8(cst[nt], al, bh0, bh1);
            }
        }

        // epilogue: +bias, LN (quad shuffles), GELU, 64->2
        float sA = 0.f, sB = 0.f;
#pragma unroll
        for (int nt = 0; nt < 8; nt++) {
            int col0 = nt * 8 + 2 * tig, col1 = col0 + 1;
            cst[nt][0] += s_b2[col0]; cst[nt][1] += s_b2[col1];
            cst[nt][2] += s_b2[col0]; cst[nt][3] += s_b2[col1];
            sA += cst[nt][0] + cst[nt][1];
            sB += cst[nt][2] + cst[nt][3];
        }
        sA += __shfl_xor_sync(0xffffffffu, sA, 1); sA += __shfl_xor_sync(0xffffffffu, sA, 2);
        sB += __shfl_xor_sync(0xffffffffu, sB, 1); sB += __shfl_xor_sync(0xffffffffu, sB, 2);
        float mA = sA * 0.015625f, mB = sB * 0.015625f;
        float qA = 0.f, qB = 0.f;
#pragma unroll
        for (int nt = 0; nt < 8; nt++) {
            float d0 = cst[nt][0] - mA, d1 = cst[nt][1] - mA;
            float d2 = cst[nt][2] - mB, d3 = cst[nt][3] - mB;
            qA += d0 * d0 + d1 * d1;
            qB += d2 * d2 + d3 * d3;
        }
        qA += __shfl_xor_sync(0xffffffffu, qA, 1); qA += __shfl_xor_sync(0xffffffffu, qA, 2);
        qB += __shfl_xor_sync(0xffffffffu, qB, 1); qB += __shfl_xor_sync(0xffffffffu, qB, 2);
        float rA = rsqrtf(qA * 0.015625f + 1e-5f);
        float rB = rsqrtf(qB * 0.015625f + 1e-5f);

        float pA0 = 0.f, pA1 = 0.f, pB0 = 0.f, pB1 = 0.f;
#pragma unroll
        for (int nt = 0; nt < 8; nt++) {
            int col0 = nt * 8 + 2 * tig, col1 = col0 + 1;
            float z;
            z = fast_gelu((cst[nt][0] - mA) * rA * s_g2[col0] + s_be2[col0]);
            pA0 += z * s_w3[2 * col0]; pA1 += z * s_w3[2 * col0 + 1];
            z = fast_gelu((cst[nt][1] - mA) * rA * s_g2[col1] + s_be2[col1]);
            pA0 += z * s_w3[2 * col1]; pA1 += z * s_w3[2 * col1 + 1];
            z = fast_gelu((cst[nt][2] - mB) * rB * s_g2[col0] + s_be2[col0]);
            pB0 += z * s_w3[2 * col0]; pB1 += z * s_w3[2 * col0 + 1];
            z = fast_gelu((cst[nt][3] - mB) * rB * s_g2[col1] + s_be2[col1]);
            pB0 += z * s_w3[2 * col1]; pB1 += z * s_w3[2 * col1 + 1];
        }
        pA0 += __shfl_xor_sync(0xffffffffu, pA0, 1); pA0 += __shfl_xor_sync(0xffffffffu, pA0, 2);
        pA1 += __shfl_xor_sync(0xffffffffu, pA1, 1); pA1 += __shfl_xor_sync(0xffffffffu, pA1, 2);
        pB0 += __shfl_xor_sync(0xffffffffu, pB0, 1); pB0 += __shfl_xor_sync(0xffffffffu, pB0, 2);
        pB1 += __shfl_xor_sync(0xffffffffu, pB1, 1); pB1 += __shfl_xor_sync(0xffffffffu, pB1, 2);

        if (tig == 0) {
            int iA = blockIdx.x * 256 + r0;
            int iB = iA + 8;
            float tA0 = pA0 + b3_0, tA1 = pA1 + b3_1;
            float tB0 = pB0 + b3_0, tB1 = pB1 + b3_1;
            if (iA < 1000) {
                g_targets[(b * 1000 + iA) * 2]     = tA0;
                g_targets[(b * 1000 + iA) * 2 + 1] = tA1;
                smAcc += sl1(tA0 - e0) + sl1(tA1 - e1);
            }
            if (iB < 1000) {
                g_targets[(b * 1000 + iB) * 2]     = tB0;
                g_targets[(b * 1000 + iB) * 2 + 1] = tB1;
                smAcc += sl1(tB0 - e0) + sl1(tB1 - e1);
            }
        }
    }

    s_red[tid] = smAcc;
    __syncthreads();
#pragma unroll
    for (int s = 128; s > 0; s >>= 1) {
        if (tid < s) s_red[tid] += s_red[tid + s];
        __syncthreads();
    }
    if (tid == 0) g_off_part[b * 4 + blockIdx.x] = s_red[0];
}

// ---------------- K3: per-batch stats, policy, top-50 ----------------
__global__ void __launch_bounds__(512) finalize_kernel(const float* __restrict__ end,
                                                       float* __restrict__ out) {
    __shared__ float s_t[2000];
    __shared__ float s_p[2000];
    __shared__ float s_pd[1024];
    __shared__ u64 s_key[1024];
    __shared__ float s_w[32];
    __shared__ int   s_wi[16];
    __shared__ float s_bc[8];
    __shared__ int s_bi;

    int b = blockIdx.x, tid = threadIdx.x;
    int wid = tid >> 5, lane = tid & 31;

    for (int i = tid; i < 2000; i += 512) {
        s_t[i] = g_targets[b * 2000 + i];
        s_p[i] = g_pts[b * 2000 + i];
    }
    __syncthreads();

    // mean (fused m0,m1) — second stage executed by ALL 32 lanes of warp 0
    float a0 = 0.f, a1 = 0.f;
    for (int i = tid; i < 1000; i += 512) { a0 += s_t[2 * i]; a1 += s_t[2 * i + 1]; }
    a0 = wsum(a0); a1 = wsum(a1);
    if (lane == 0) { s_w[wid] = a0; s_w[16 + wid] = a1; }
    __syncthreads();
    if (tid < 32) {
        float v = s_w[tid];
        v += __shfl_xor_sync(0xffffffffu, v, 8);
        v += __shfl_xor_sync(0xffffffffu, v, 4);
        v += __shfl_xor_sync(0xffffffffu, v, 2);
        v += __shfl_xor_sync(0xffffffffu, v, 1);
        if ((tid & 15) == 0) s_bc[tid >> 4] = v * 0.001f;
    }
    __syncthreads();
    float m0 = s_bc[0], m1 = s_bc[1];

    // var (ddof=1), fused
    float q0 = 0.f, q1 = 0.f;
    for (int i = tid; i < 1000; i += 512) {
        float d0 = s_t[2 * i] - m0, d1 = s_t[2 * i + 1] - m1;
        q0 += d0 * d0; q1 += d1 * d1;
    }
    q0 = wsum(q0); q1 = wsum(q1);
    if (lane == 0) { s_w[wid] = q0; s_w[16 + wid] = q1; }
    __syncthreads();
    if (tid < 32) {
        float v = s_w[tid];
        v += __shfl_xor_sync(0xffffffffu, v, 8);
        v += __shfl_xor_sync(0xffffffffu, v, 4);
        v += __shfl_xor_sync(0xffffffffu, v, 2);
        v += __shfl_xor_sync(0xffffffffu, v, 1);
        if ((tid & 15) == 0) s_bc[2 + (tid >> 4)] = v / 999.0f;
    }
    __syncthreads();
    float v0 = s_bc[2], v1 = s_bc[3];

    // policy_dist
    float den0 = sqrtf(6.2831853071795864f * v0 + 1e-6f);
    float den1 = sqrtf(6.2831853071795864f * v1 + 1e-6f);
    for (int i = tid; i < 1024; i += 512) {
        float pd = -1.0f;
        if (i < 1000) {
            float dx = s_t[2 * i] - m0, dy = s_t[2 * i + 1] - m1;
            float pdx = expf(-0.5f * dx * dx / v0 + 1e-6f) / den0;
            float pdy = expf(-0.5f * dy * dy / v1 + 1e-6f) / den1;
            pd = pdx * pdy;
        }
        s_pd[i] = pd;
    }
    __syncthreads();

    // max(pd) — full warp 0 with identity padding (FIX for R3 hang)
    float mx = -1.0f;
    for (int i = tid; i < 1000; i += 512) mx = fmaxf(mx, s_pd[i]);
#pragma unroll
    for (int o = 16; o; o >>= 1) mx = fmaxf(mx, __shfl_xor_sync(0xffffffffu, mx, o));
    if (lane == 0) s_w[wid] = mx;
    __syncthreads();
    if (tid < 32) {
        float v = (tid < 16) ? s_w[tid] : -3.4e38f;
        v = fmaxf(v, __shfl_xor_sync(0xffffffffu, v, 8));
        v = fmaxf(v, __shfl_xor_sync(0xffffffffu, v, 4));
        v = fmaxf(v, __shfl_xor_sync(0xffffffffu, v, 2));
        v = fmaxf(v, __shfl_xor_sync(0xffffffffu, v, 1));
        if (tid == 0) s_bc[4] = v;
    }
    __syncthreads();
    mx = s_bc[4];

    // sum exp(pd - mx) — full warp 0 with identity padding (FIX)
    float se = 0.f;
    for (int i = tid; i < 1000; i += 512) se += expf(s_pd[i] - mx);
    se = wsum(se);
    if (lane == 0) s_w[wid] = se;
    __syncthreads();
    if (tid < 32) {
        float v = (tid < 16) ? s_w[tid] : 0.0f;
        v += __shfl_xor_sync(0xffffffffu, v, 8);
        v += __shfl_xor_sync(0xffffffffu, v, 4);
        v += __shfl_xor_sync(0xffffffffu, v, 2);
        v += __shfl_xor_sync(0xffffffffu, v, 1);
        if (tid == 0) s_bc[5] = v;
    }
    __syncthreads();
    float lse = mx + logf(s_bc[5]);

    // argmin distance to end (first-index tiebreak) — full warp 0 (FIX)
    float e0 = end[2 * b], e1 = end[2 * b + 1];
    float bd = 3.4e38f; int bi = 0x7fffffff;
    for (int i = tid; i < 1000; i += 512) {
        float dx = s_p[2 * i] - e0;
        float dy = s_p[2 * i + 1] - e1;
        float ds = sqrtf(dx * dx + dy * dy);
        if (ds < bd || (ds == bd && i < bi)) { bd = ds; bi = i; }
    }
#pragma unroll
    for (int o = 16; o; o >>= 1) {
        float od = __shfl_xor_sync(0xffffffffu, bd, o);
        int   oi = __shfl_xor_sync(0xffffffffu, bi, o);
        if (od < bd || (od == bd && oi < bi)) { bd = od; bi = oi; }
    }
    if (lane == 0) { s_w[wid] = bd; s_wi[wid] = bi; }
    __syncthreads();
    if (tid < 32) {
        float v  = (tid < 16) ? s_w[tid]  : 3.4e38f;
        int   vi = (tid < 16) ? s_wi[tid] : 0x7fffffff;
#pragma unroll
        for (int o = 8; o; o >>= 1) {
            float od = __shfl_xor_sync(0xffffffffu, v, o);
            int   oi = __shfl_xor_sync(0xffffffffu, vi, o);
            if (od < v || (od == v && oi < vi)) { v = od; vi = oi; }
        }
        if (tid == 0) s_bi = vi;
    }
    __syncthreads();
    float picked = s_pd[s_bi];

    // top-50 by pd desc, stable by index (bitonic)
    for (int i = tid; i < 1024; i += 512) {
        u32 pb = (i < 1000) ? __float_as_uint(s_pd[i]) : 0u;
        s_key[i] = ((u64)(0xFFFFFFFFu - pb) << 32) | (u32)i;
    }
    bool lastBig = true;
    for (int k = 2; k <= 1024; k <<= 1) {
        for (int j = k >> 1; j > 0; j >>= 1) {
            bool big = (j >= 64);
            if (big || lastBig) __syncthreads(); else __syncwarp();
            int i0 = ((tid & ~(j - 1)) << 1) | (tid & (j - 1));
            int i1 = i0 | j;
            bool up = ((i0 & k) == 0);
            u64 A = s_key[i0], B = s_key[i1];
            if ((A > B) == up) { s_key[i0] = B; s_key[i1] = A; }
            lastBig = big;
        }
    }
    __syncthreads();

    float es = 0.f;
    if (tid < 50) {
        int id = (int)(u32)(s_key[tid] & 0xffffffffull);
        float t0 = s_t[2 * id], t1 = s_t[2 * id + 1];
        out[2 + (b * 50 + tid) * 2]     = t0;
        out[2 + (b * 50 + tid) * 2 + 1] = t1;
        es = sl1(t0 - e0) + sl1(t1 - e1);
    }
    es = wsum(es);
    if (lane == 0) s_w[wid] = es;
    __syncthreads();
    if (tid == 0) {
        float tot = 0.f;
#pragma unroll
        for (int w = 0; w < 16; w++) tot += s_w[w];
        g_cls[b] = lse - picked;
        g_endsum[b] = tot;
    }
}

// ---------------- K4: final scalar reductions ----------------
__global__ void __launch_bounds__(512) reduce_kernel(float* __restrict__ out) {
    __shared__ float r[512];
    int tid = threadIdx.x;
    float offs = 0.f;
    for (int i = tid; i < 2048; i += 512) offs += g_off_part[i];
    float cls = g_cls[tid];
    float ends = g_endsum[tid];

    r[tid] = offs; __syncthreads();
    for (int s = 256; s > 0; s >>= 1) { if (tid < s) r[tid] += r[tid + s]; __syncthreads(); }
    float offT = r[0]; __syncthreads();
    r[tid] = cls; __syncthreads();
    for (int s = 256; s > 0; s >>= 1) { if (tid < s) r[tid] += r[tid + s]; __syncthreads(); }
    float clsT = r[0]; __syncthreads();
    r[tid] = ends; __syncthreads();
    for (int s = 256; s > 0; s >>= 1) { if (tid < s) r[tid] += r[tid + s]; __syncthreads(); }
    float endT = r[0];

    if (tid == 0) {
        out[0] = clsT / 512.0f;
        out[1] = offT / 1024000.0f + 3.0f * (endT / 51200.0f);
    }
}

extern "C" void kernel_launch(void* const* d_in, const int* in_sizes, int n_in,
                              void* d_out, int out_size) {
    const float* osm   = (const float*)d_in[0];
    const float* at    = (const float*)d_in[1];
    const float* vf    = (const float*)d_in[2];
    const float* end   = (const float*)d_in[3];
    const float* ox_w1 = (const float*)d_in[5];
    const float* ox_b1 = (const float*)d_in[6];
    const float* ox_g1 = (const float*)d_in[7];
    const float* ox_be1= (const float*)d_in[8];
    const float* ox_w2 = (const float*)d_in[9];
    const float* ox_b2 = (const float*)d_in[10];
    const float* tp_w1 = (const float*)d_in[11];
    const float* tp_b1 = (const float*)d_in[12];
    const float* tp_g1 = (const float*)d_in[13];
    const float* tp_be1= (const float*)d_in[14];
    const float* tp_w2 = (const float*)d_in[15];
    const float* tp_b2 = (const float*)d_in[16];
    const float* tp_g2 = (const float*)d_in[17];
    const float* tp_be2= (const float*)d_in[18];
    const float* tp_w3 = (const float*)d_in[19];
    const float* tp_b3 = (const float*)d_in[20];
    float* out = (float*)d_out;

    cudaFuncSetAttribute(mlp_kernel, cudaFuncAttributeMaxDynamicSharedMemorySize, MLP_DSMEM);

    precompute_kernel<<<512, 256>>>(at, vf, ox_w1, ox_b1, tp_w1, tp_b1);
    select_kernel<<<512, 1024>>>(osm);
    dim3 g(4, 512);
    mlp_kernel<<<g, 256, MLP_DSMEM>>>(ox_w1, ox_g1, ox_be1, ox_w2, ox_b2,
                                      tp_w1, tp_g1, tp_be1, tp_w2, tp_b2,
                                      tp_g2, tp_be2, tp_w3, tp_b3, end);
    finalize_kernel<<<512, 512>>>(end, out);
    reduce_kernel<<<1, 512>>>(out);
}